// round 12
// baseline (speedup 1.0000x reference)
#include <cuda_runtime.h>
#include <cuda_bf16.h>
#include <cstdint>

#define DIM      4096
#define NUMEL    (DIM*DIM)
#define KTOT     8388608u
#define KB_TOT   2048
#define NBINS    8192
#define CAP      16384
#define SEL_SMEM  (CAP*8 + 4096*4)

// GEMM: 256x128 tile, 512 threads (16 warps 4x4), K=64/stage, 4 bufs (R6 config)
#define FM       256
#define FN       128
#define NSTAGE_F 192
#define FA_SZ    (FM*128)
#define FB_SZ    (FN*128)
#define FS_SZ    (FA_SZ+FB_SZ)     // 49152
#define FB_SMEM  (1024 + 4*FS_SZ)  // 197632

#define SOFF(r,c) ((uint32_t)((r)*128 + (((c) ^ ((r)&7))*16)))

__device__ __nv_bfloat16 g_A0[(size_t)DIM*8192];
__device__ __nv_bfloat16 g_A1[(size_t)DIM*8192];
__device__ __nv_bfloat16 g_WmA[(size_t)DIM*8192];
__device__ __nv_bfloat16 g_WmB[(size_t)DIM*8192];
__device__ float g_bmA[DIM];
__device__ float g_bmB[DIM];
__device__ unsigned int g_hist[NBINS];
__device__ int   g_binstar, g_cbefore, g_cand_cnt, g_spec_ok;
__device__ float g_cand_val[CAP];
__device__ int   g_cand_idx[CAP];
__device__ float g_tval;
__device__ int   g_tidx;

__device__ __forceinline__ uint32_t smem_u32(const void* p) {
    uint32_t a;
    asm("{ .reg .u64 t; cvta.to.shared.u64 t, %1; cvt.u32.u64 %0, t; }" : "=r"(a) : "l"(p));
    return a;
}
__device__ __forceinline__ void cp16(uint32_t dst, const void* src) {
    asm volatile("cp.async.cg.shared.global [%0], [%1], 16;" :: "r"(dst), "l"(src));
}
#define CP_COMMIT() asm volatile("cp.async.commit_group;" ::: "memory")
#define CP_WAIT(n)  asm volatile("cp.async.wait_group %0;" :: "n"(n) : "memory")

__device__ __forceinline__ int qval(float v) {
    int q = (int)(v * 33554432.0f);
    return q < 0 ? 0 : (q > 33554431 ? 33554431 : q);
}
__device__ __forceinline__ void split_bf16(float v, unsigned short& h, unsigned short& l) {
    __nv_bfloat16 hb = __float2bfloat16(v);
    __nv_bfloat16 lb = __float2bfloat16(v - __bfloat162float(hb));
    h = __bfloat16_as_ushort(hb); l = __bfloat16_as_ushort(lb);
}
__device__ __forceinline__ unsigned int block_excl_scan(unsigned int val, unsigned int* wsum) {
    int lane = threadIdx.x & 31, warp = threadIdx.x >> 5;
    unsigned int v = val;
    #pragma unroll
    for (int o = 1; o < 32; o <<= 1) {
        unsigned int n = __shfl_up_sync(0xFFFFFFFFu, v, o);
        if (lane >= o) v += n;
    }
    if (lane == 31) wsum[warp] = v;
    __syncthreads();
    if (warp == 0) {
        unsigned int w = wsum[lane];
        #pragma unroll
        for (int o = 1; o < 32; o <<= 1) {
            unsigned int n = __shfl_up_sync(0xFFFFFFFFu, w, o);
            if (lane >= o) w += n;
        }
        wsum[lane] = w;
    }
    __syncthreads();
    return (warp ? wsum[warp-1] : 0u) + v - val;
}

// ---------------- masking pipeline ----------------
__global__ void clear_kernel() {
    for (int i = threadIdx.x; i < NBINS; i += 1024) g_hist[i] = 0;
    if (threadIdx.x == 0) g_cand_cnt = 0;
}

__global__ void hist_kernel(const float4* __restrict__ M4) {
    __shared__ unsigned int h[NBINS];
    for (int i = threadIdx.x; i < NBINS; i += 256) h[i] = 0;
    __syncthreads();
    int stride = gridDim.x * blockDim.x;
    for (int i = blockIdx.x*blockDim.x + threadIdx.x; i < NUMEL/4; i += stride) {
        float4 v = M4[i];
        float vv[4] = {v.x, v.y, v.z, v.w};
        #pragma unroll
        for (int j = 0; j < 4; j++) {
            int q = qval(vv[j]), bb = q >> 12;
            atomicAdd(&h[bb], 1u);
            if (bb >= 4095 && bb <= 4097) {
                int p = atomicAdd(&g_cand_cnt, 1);
                if (p < CAP) { g_cand_val[p] = vv[j]; g_cand_idx[p] = i*4+j; }
            }
        }
    }
    __syncthreads();
    for (int i = threadIdx.x; i < NBINS; i += 256)
        if (h[i]) atomicAdd(&g_hist[i], h[i]);
}

__global__ void scan_kernel() {
    __shared__ unsigned int wsum[32];
    int t = threadIdx.x;
    unsigned int c8[8], s = 0;
    #pragma unroll
    for (int j = 0; j < 8; j++) { c8[j] = g_hist[t*8+j]; s += c8[j]; }
    unsigned int run = block_excl_scan(s, wsum);
    #pragma unroll
    for (int j = 0; j < 8; j++) {
        unsigned int c = c8[j];
        if (run < KTOT && run + c >= KTOT) {
            int bs = t*8+j;
            g_binstar = bs; g_cbefore = (int)run;
            int ok = (bs >= 4095 && bs <= 4097 && g_cand_cnt <= CAP) ? 1 : 0;
            g_spec_ok = ok;
            if (!ok) g_cand_cnt = 0;
        }
        run += c;
    }
}

__global__ void gather_kernel(const float4* __restrict__ M4) {
    if (g_spec_ok) return;
    int bstar = g_binstar;
    int stride = gridDim.x * blockDim.x;
    for (int i = blockIdx.x*blockDim.x + threadIdx.x; i < NUMEL/4; i += stride) {
        float4 v = M4[i];
        float vv[4] = {v.x, v.y, v.z, v.w};
        #pragma unroll
        for (int j = 0; j < 4; j++)
            if ((qval(vv[j])>>12) == bstar) {
                int p = atomicAdd(&g_cand_cnt, 1);
                if (p < CAP) { g_cand_val[p] = vv[j]; g_cand_idx[p] = i*4+j; }
            }
    }
}

__global__ void select_kernel() {
    extern __shared__ char sm[];
    float* sv = (float*)sm;
    int* si = (int*)(sm + CAP*4);
    unsigned int* sh = (unsigned int*)(sm + CAP*8);
    __shared__ unsigned int wsum[32];
    __shared__ int s_b2, s_need2;
    int t = threadIdx.x;
    int c = g_cand_cnt; if (c > CAP) c = CAP;
    int need = (int)KTOT - g_cbefore;
    int bstar = g_binstar;
    for (int i = t; i < c; i += 1024) { sv[i] = g_cand_val[i]; si[i] = g_cand_idx[i]; }
    for (int i = t; i < 4096; i += 1024) sh[i] = 0;
    __syncthreads();
    for (int i = t; i < c; i += 1024) {
        int q = qval(sv[i]);
        if ((q >> 12) == bstar) atomicAdd(&sh[q & 4095], 1u);
    }
    __syncthreads();
    unsigned int c4[4], s = 0;
    #pragma unroll
    for (int j = 0; j < 4; j++) { c4[j] = sh[t*4+j]; s += c4[j]; }
    unsigned int run = block_excl_scan(s, wsum);
    #pragma unroll
    for (int j = 0; j < 4; j++) {
        unsigned int cc = c4[j];
        if (run < (unsigned)need && run + cc >= (unsigned)need) { s_b2 = t*4+j; s_need2 = need - (int)run; }
        run += cc;
    }
    __syncthreads();
    int b2 = s_b2, need2 = s_need2;
    for (int j = t; j < c; j += 1024) {
        float vj = sv[j];
        int qj = qval(vj);
        if ((qj >> 12) != bstar || (qj & 4095) != b2) continue;
        int ij = si[j], cnt = 0;
        for (int i = 0; i < c; i++) {
            float v = sv[i];
            int qi = qval(v);
            if ((qi >> 12) != bstar || (qi & 4095) != b2) continue;
            cnt += (v < vj) || (v == vj && si[i] < ij);
        }
        if (cnt == need2 - 1) { g_tval = vj; g_tidx = ij; }
    }
}

__global__ void biasmask_kernel(const float* __restrict__ b, const float* __restrict__ mb,
                                float* __restrict__ bmo) {
    __shared__ float svv[DIM];
    int t = threadIdx.x, j = blockIdx.x*256 + t;
    for (int i = t; i < DIM; i += 256) svv[i] = mb[i];
    __syncthreads();
    float vj = svv[j];
    int cnt = 0;
    for (int i = 0; i < DIM; i++) { float v = svv[i]; cnt += (v < vj) || (v == vj && i < j); }
    bmo[j] = (cnt < KB_TOT) ? 0.0f : b[j];
}

__global__ void maskconv_kernel(const float4* __restrict__ W4, const float4* __restrict__ M4,
                                unsigned short* __restrict__ Wo) {
    float tv = g_tval; int ti = g_tidx;
    int stride = gridDim.x * blockDim.x;
    for (int i = blockIdx.x*blockDim.x + threadIdx.x; i < NUMEL/4; i += stride) {
        float4 w = W4[i]; float4 m = M4[i];
        float wv[4] = {w.x, w.y, w.z, w.w};
        float mv[4] = {m.x, m.y, m.z, m.w};
        int e0 = i*4;
        unsigned short hh[4], ll[4];
        #pragma unroll
        for (int j = 0; j < 4; j++) {
            bool z = (mv[j] < tv) || (mv[j] == tv && (e0+j) <= ti);
            split_bf16(z ? 0.0f : wv[j], hh[j], ll[j]);
        }
        size_t base = (size_t)(e0>>12)*8192 + (e0 & 4095);
        *(ushort4*)(Wo + base)        = make_ushort4(hh[0],hh[1],hh[2],hh[3]);
        *(ushort4*)(Wo + base + 4096) = make_ushort4(ll[0],ll[1],ll[2],ll[3]);
    }
}

__global__ void split_x_kernel(const float4* __restrict__ x4) {
    int stride = gridDim.x * blockDim.x;
    unsigned short* Ao = (unsigned short*)g_A0;
    for (int i = blockIdx.x*blockDim.x + threadIdx.x; i < NUMEL/4; i += stride) {
        float4 v = x4[i];
        float vv[4] = {v.x, v.y, v.z, v.w};
        unsigned short hh[4], ll[4];
        #pragma unroll
        for (int j = 0; j < 4; j++) split_bf16(vv[j], hh[j], ll[j]);
        int e0 = i*4;
        size_t base = (size_t)(e0>>12)*8192 + (e0 & 4095);
        *(ushort4*)(Ao + base)        = make_ushort4(hh[0],hh[1],hh[2],hh[3]);
        *(ushort4*)(Ao + base + 4096) = make_ushort4(ll[0],ll[1],ll[2],ll[3]);
    }
}

// ---------------- GEMM: mma.sync bf16, 256x128 tile, K=64/stage (R6) ----------------
#define LDSM4(r, a) asm volatile("ldmatrix.sync.aligned.m8n8.x4.shared.b16 {%0,%1,%2,%3}, [%4];" \
    : "=r"((r)[0]),"=r"((r)[1]),"=r"((r)[2]),"=r"((r)[3]) : "r"(a))
#define MMA16816(acc, a, b0, b1) asm volatile( \
    "mma.sync.aligned.m16n8k16.row.col.f32.bf16.bf16.f32 {%0,%1,%2,%3},{%4,%5,%6,%7},{%8,%9},{%0,%1,%2,%3};" \
    : "+f"((acc)[0]),"+f"((acc)[1]),"+f"((acc)[2]),"+f"((acc)[3]) \
    : "r"((a)[0]),"r"((a)[1]),"r"((a)[2]),"r"((a)[3]),"r"(b0),"r"(b1))

template <bool FINAL>
__global__ void __launch_bounds__(512, 1) gemm_fb(
    const __nv_bfloat16* __restrict__ A, const __nv_bfloat16* __restrict__ W,
    const float* __restrict__ bias,
    unsigned short* __restrict__ outb, float* __restrict__ outf)
{
    extern __shared__ char smem[];
    uint32_t sb = smem_u32(smem);
    float* sbias = (float*)smem;
    int tid = threadIdx.x, wid = tid >> 5, lane = tid & 31;
    int mw = wid >> 2, nw = wid & 3;
    int tn = blockIdx.x, tm = blockIdx.y;
    if (tid < FN) sbias[tid] = bias[tn*FN + tid];

    const char* Ab = (const char*)A;
    const char* Wb = (const char*)W;

    float acc[4][4][4];
    #pragma unroll
    for (int i = 0; i < 4; i++)
        #pragma unroll
        for (int j = 0; j < 4; j++)
            #pragma unroll
            for (int k = 0; k < 4; k++) acc[i][j][k] = 0.f;

    #define FLOAD(s) do { \
        int seg_ = (s) >> 6, kk_ = ((s) & 63) << 6; \
        int aoff_ = (seg_ == 1 ? 4096 : 0) + kk_; \
        int boff_ = (seg_ == 2 ? 4096 : 0) + kk_; \
        uint32_t stg_ = sb + 1024 + ((s) & 3) * FS_SZ; \
        for (int u = tid; u < 3072; u += 512) { \
            if (u < 2048) { int r_ = u >> 3, c_ = u & 7; \
                cp16(stg_ + SOFF(r_, c_), Ab + (((size_t)(tm*FM + r_))*8192 + aoff_ + c_*8)*2); \
            } else { int v_ = u - 2048, r_ = v_ >> 3, c_ = v_ & 7; \
                cp16(stg_ + FA_SZ + SOFF(r_, c_), Wb + (((size_t)(tn*FN + r_))*8192 + boff_ + c_*8)*2); } \
        } \
        CP_COMMIT(); \
    } while (0)

    FLOAD(0); FLOAD(1); FLOAD(2);

    int rA = mw*64 + (lane & 15);
    int rB = nw*32 + (lane & 15);
    int chh = lane >> 4;

    for (int s = 0; s < NSTAGE_F; s++) {
        if (s < NSTAGE_F-2)       { CP_WAIT(2); }
        else if (s == NSTAGE_F-2) { CP_WAIT(1); }
        else                      { CP_WAIT(0); }
        __syncthreads();
        if (s + 3 < NSTAGE_F) FLOAD(s + 3);
        uint32_t astg = sb + 1024 + (s & 3) * FS_SZ;
        uint32_t bstg = astg + FA_SZ;
        #pragma unroll
        for (int ks = 0; ks < 4; ks++) {
            int ch = ks*2 + chh;
            uint32_t a[4][4], b[2][4];
            #pragma unroll
            for (int mt = 0; mt < 4; mt++) LDSM4(a[mt], astg + SOFF(rA + mt*16, ch));
            #pragma unroll
            for (int nt = 0; nt < 2; nt++) LDSM4(b[nt], bstg + SOFF(rB + nt*16, ch));
            #pragma unroll
            for (int mt = 0; mt < 4; mt++)
                #pragma unroll
                for (int nt = 0; nt < 2; nt++)
                    #pragma unroll
                    for (int h = 0; h < 2; h++)
                        MMA16816(acc[mt][nt*2+h], a[mt], b[nt][h], b[nt][h+2]);
        }
    }

    int mwb = tm*FM + mw*64;
    #pragma unroll
    for (int mt = 0; mt < 4; mt++)
        #pragma unroll
        for (int nt = 0; nt < 2; nt++)
            #pragma unroll
            for (int h = 0; h < 2; h++) {
                float* c = acc[mt][nt*2+h];
                int m0 = mwb + mt*16 + (lane >> 2);
                int nl = nw*32 + nt*16 + h*8 + (lane & 3)*2;
                int ng = tn*FN + nl;
                float b0 = sbias[nl], b1 = sbias[nl+1];
                #pragma unroll
                for (int rr = 0; rr < 2; rr++) {
                    int m = m0 + rr*8;
                    float v0 = c[rr*2+0] + b0, v1 = c[rr*2+1] + b1;
                    if (!FINAL) {
                        unsigned short h0, l0, h1, l1;
                        split_bf16(fmaxf(v0, 0.f), h0, l0);
                        split_bf16(fmaxf(v1, 0.f), h1, l1);
                        size_t base = (size_t)m*8192 + ng;
                        *(unsigned int*)(outb + base)        = (unsigned int)h0 | ((unsigned int)h1 << 16);
                        *(unsigned int*)(outb + base + 4096) = (unsigned int)l0 | ((unsigned int)l1 << 16);
                    } else {
                        *(float2*)(outf + (size_t)m*4096 + ng) = make_float2(v0, v1);
                    }
                }
            }
}

// ---------------- launch: fork-join overlap of masking and GEMM ----------------
extern "C" void kernel_launch(void* const* d_in, const int* in_sizes, int n_in,
                              void* d_out, int out_size) {
    (void)in_sizes; (void)n_in; (void)out_size;
    cudaFuncSetAttribute(select_kernel, cudaFuncAttributeMaxDynamicSharedMemorySize, SEL_SMEM);
    cudaFuncSetAttribute(gemm_fb<false>, cudaFuncAttributeMaxDynamicSharedMemorySize, FB_SMEM);
    cudaFuncSetAttribute(gemm_fb<true>,  cudaFuncAttributeMaxDynamicSharedMemorySize, FB_SMEM);

    void *pA0, *pA1, *pWA, *pWB, *pBA, *pBB;
    cudaGetSymbolAddress(&pA0, g_A0);
    cudaGetSymbolAddress(&pA1, g_A1);
    cudaGetSymbolAddress(&pWA, g_WmA);
    cudaGetSymbolAddress(&pWB, g_WmB);
    cudaGetSymbolAddress(&pBA, g_bmA);
    cudaGetSymbolAddress(&pBB, g_bmB);
    __nv_bfloat16* abuf[2] = {(__nv_bfloat16*)pA0, (__nv_bfloat16*)pA1};
    __nv_bfloat16* wbuf[2] = {(__nv_bfloat16*)pWA, (__nv_bfloat16*)pWB};
    float*         bbuf[2] = {(float*)pBA, (float*)pBB};

    cudaStream_t s2;
    cudaStreamCreateWithFlags(&s2, cudaStreamNonBlocking);
    cudaEvent_t evRoot, evM[4], evG[2];
    cudaEventCreateWithFlags(&evRoot, cudaEventDisableTiming);
    for (int l = 0; l < 4; l++) cudaEventCreateWithFlags(&evM[l], cudaEventDisableTiming);
    for (int l = 0; l < 2; l++) cudaEventCreateWithFlags(&evG[l], cudaEventDisableTiming);

    // fork side stream off the main (capture) stream
    cudaEventRecord(evRoot, 0);
    cudaStreamWaitEvent(s2, evRoot, 0);

    auto mask = [&](int l) {
        const float* W  = (const float*)d_in[1 + l*4 + 0];
        const float* b  = (const float*)d_in[1 + l*4 + 1];
        const float* M  = (const float*)d_in[1 + l*4 + 2];
        const float* mb = (const float*)d_in[1 + l*4 + 3];
        clear_kernel<<<1, 1024, 0, s2>>>();
        hist_kernel<<<1024, 256, 0, s2>>>((const float4*)M);
        scan_kernel<<<1, 1024, 0, s2>>>();
        gather_kernel<<<1024, 256, 0, s2>>>((const float4*)M);
        select_kernel<<<1, 1024, SEL_SMEM, s2>>>();
        biasmask_kernel<<<16, 256, 0, s2>>>(b, mb, bbuf[l & 1]);
        maskconv_kernel<<<1024, 256, 0, s2>>>((const float4*)W, (const float4*)M,
                                              (unsigned short*)wbuf[l & 1]);
        cudaEventRecord(evM[l], s2);
    };

    dim3 gf(DIM/FN, DIM/FM);   // 32 x 16 = 512 CTAs

    mask(0);
    mask(1);
    split_x_kernel<<<1024, 256>>>((const float4*)d_in[0]);

    // layer 0
    cudaStreamWaitEvent(0, evM[0], 0);
    gemm_fb<false><<<gf, 512, FB_SMEM>>>(abuf[0], wbuf[0], bbuf[0],
                                         (unsigned short*)abuf[1], nullptr);
    cudaEventRecord(evG[0], 0);
    cudaStreamWaitEvent(s2, evG[0], 0);   // buffer 0 free for layer 2's mask
    mask(2);

    // layer 1
    cudaStreamWaitEvent(0, evM[1], 0);
    gemm_fb<false><<<gf, 512, FB_SMEM>>>(abuf[1], wbuf[1], bbuf[1],
                                         (unsigned short*)abuf[0], nullptr);
    cudaEventRecord(evG[1], 0);
    cudaStreamWaitEvent(s2, evG[1], 0);   // buffer 1 free for layer 3's mask
    mask(3);

    // layer 2
    cudaStreamWaitEvent(0, evM[2], 0);
    gemm_fb<false><<<gf, 512, FB_SMEM>>>(abuf[0], wbuf[0], bbuf[0],
                                         (unsigned short*)abuf[1], nullptr);

    // layer 3 (joins side stream back into the capture stream)
    cudaStreamWaitEvent(0, evM[3], 0);
    gemm_fb<true><<<gf, 512, FB_SMEM>>>(abuf[1], wbuf[1], bbuf[1],
                                        nullptr, (float*)d_out);
}

// round 14
// speedup vs baseline: 1.2220x; 1.2220x over previous
#include <cuda_runtime.h>
#include <cuda_bf16.h>
#include <cuda_fp16.h>
#include <cstdint>

#define DIM      4096
#define NUMEL    (DIM*DIM)
#define KTOT     8388608u
#define KB_TOT   2048
#define NBINS    8192
#define CAP      16384
#define SEL_SMEM  (CAP*8 + 4096*4)

// GEMM: 256x128 tile, 512 threads (16 warps 4x4), K=64/stage, 4 bufs
// ext-K = 8192: seg0=(Ah,Bh) seg1=(Al,Bh); fp16 limbs, fp32 accum
#define FM       256
#define FN       128
#define NSTAGE_F 128
#define FA_SZ    (FM*128)
#define FB_SZ    (FN*128)
#define FS_SZ    (FA_SZ+FB_SZ)     // 49152
#define FB_SMEM  (1024 + 4*FS_SZ)  // 197632

#define SOFF(r,c) ((uint32_t)((r)*128 + (((c) ^ ((r)&7))*16)))

__device__ __half g_A0[(size_t)DIM*8192];   // activations [hi(4096)|lo(4096)] fp16
__device__ __half g_A1[(size_t)DIM*8192];
__device__ __half g_Wm[(size_t)DIM*4096];   // masked weights, single fp16 limb
__device__ unsigned int g_hist[NBINS];
__device__ int   g_binstar, g_cbefore, g_cand_cnt, g_spec_ok;
__device__ float g_cand_val[CAP];
__device__ int   g_cand_idx[CAP];
__device__ float g_tval;
__device__ int   g_tidx;
__device__ float g_bm[DIM];

__device__ __forceinline__ uint32_t smem_u32(const void* p) {
    uint32_t a;
    asm("{ .reg .u64 t; cvta.to.shared.u64 t, %1; cvt.u32.u64 %0, t; }" : "=r"(a) : "l"(p));
    return a;
}
__device__ __forceinline__ void cp16(uint32_t dst, const void* src) {
    asm volatile("cp.async.cg.shared.global [%0], [%1], 16;" :: "r"(dst), "l"(src));
}
#define CP_COMMIT() asm volatile("cp.async.commit_group;" ::: "memory")
#define CP_WAIT(n)  asm volatile("cp.async.wait_group %0;" :: "n"(n) : "memory")

__device__ __forceinline__ int qval(float v) {
    int q = (int)(v * 33554432.0f);
    return q < 0 ? 0 : (q > 33554431 ? 33554431 : q);
}
__device__ __forceinline__ void split_fp16(float v, unsigned short& h, unsigned short& l) {
    __half hb = __float2half(v);
    __half lb = __float2half(v - __half2float(hb));
    h = __half_as_ushort(hb); l = __half_as_ushort(lb);
}
__device__ __forceinline__ unsigned int block_excl_scan(unsigned int val, unsigned int* wsum) {
    int lane = threadIdx.x & 31, warp = threadIdx.x >> 5;
    unsigned int v = val;
    #pragma unroll
    for (int o = 1; o < 32; o <<= 1) {
        unsigned int n = __shfl_up_sync(0xFFFFFFFFu, v, o);
        if (lane >= o) v += n;
    }
    if (lane == 31) wsum[warp] = v;
    __syncthreads();
    if (warp == 0) {
        unsigned int w = wsum[lane];
        #pragma unroll
        for (int o = 1; o < 32; o <<= 1) {
            unsigned int n = __shfl_up_sync(0xFFFFFFFFu, w, o);
            if (lane >= o) w += n;
        }
        wsum[lane] = w;
    }
    __syncthreads();
    return (warp ? wsum[warp-1] : 0u) + v - val;
}

// ---------------- masking pipeline ----------------
__global__ void clear_kernel() {
    for (int i = threadIdx.x; i < NBINS; i += 1024) g_hist[i] = 0;
    if (threadIdx.x == 0) g_cand_cnt = 0;
}

// histogram + speculative candidate gather for bins 4095..4097 (threshold ~ median)
__global__ void hist_kernel(const float4* __restrict__ M4) {
    __shared__ unsigned int h[NBINS];
    for (int i = threadIdx.x; i < NBINS; i += 256) h[i] = 0;
    __syncthreads();
    int stride = gridDim.x * blockDim.x;
    for (int i = blockIdx.x*blockDim.x + threadIdx.x; i < NUMEL/4; i += stride) {
        float4 v = M4[i];
        float vv[4] = {v.x, v.y, v.z, v.w};
        #pragma unroll
        for (int j = 0; j < 4; j++) {
            int q = qval(vv[j]), bb = q >> 12;
            atomicAdd(&h[bb], 1u);
            if (bb >= 4095 && bb <= 4097) {
                int p = atomicAdd(&g_cand_cnt, 1);
                if (p < CAP) { g_cand_val[p] = vv[j]; g_cand_idx[p] = i*4+j; }
            }
        }
    }
    __syncthreads();
    for (int i = threadIdx.x; i < NBINS; i += 256)
        if (h[i]) atomicAdd(&g_hist[i], h[i]);
}

__global__ void scan_kernel() {
    __shared__ unsigned int wsum[32];
    int t = threadIdx.x;
    unsigned int c8[8], s = 0;
    #pragma unroll
    for (int j = 0; j < 8; j++) { c8[j] = g_hist[t*8+j]; s += c8[j]; }
    unsigned int run = block_excl_scan(s, wsum);
    #pragma unroll
    for (int j = 0; j < 8; j++) {
        unsigned int c = c8[j];
        if (run < KTOT && run + c >= KTOT) {
            int bs = t*8+j;
            g_binstar = bs; g_cbefore = (int)run;
            int ok = (bs >= 4095 && bs <= 4097 && g_cand_cnt <= CAP) ? 1 : 0;
            g_spec_ok = ok;
            if (!ok) g_cand_cnt = 0;   // speculation missed: regather exactly
        }
        run += c;
    }
}

__global__ void gather_kernel(const float4* __restrict__ M4) {
    if (g_spec_ok) return;
    int bstar = g_binstar;
    int stride = gridDim.x * blockDim.x;
    for (int i = blockIdx.x*blockDim.x + threadIdx.x; i < NUMEL/4; i += stride) {
        float4 v = M4[i];
        float vv[4] = {v.x, v.y, v.z, v.w};
        #pragma unroll
        for (int j = 0; j < 4; j++)
            if ((qval(vv[j])>>12) == bstar) {
                int p = atomicAdd(&g_cand_cnt, 1);
                if (p < CAP) { g_cand_val[p] = vv[j]; g_cand_idx[p] = i*4+j; }
            }
    }
}

// exact stable-rank selection inside boundary bin (filters non-binstar candidates)
__global__ void select_kernel() {
    extern __shared__ char sm[];
    float* sv = (float*)sm;
    int* si = (int*)(sm + CAP*4);
    unsigned int* sh = (unsigned int*)(sm + CAP*8);
    __shared__ unsigned int wsum[32];
    __shared__ int s_b2, s_need2;
    int t = threadIdx.x;
    int c = g_cand_cnt; if (c > CAP) c = CAP;
    int need = (int)KTOT - g_cbefore;
    int bstar = g_binstar;
    for (int i = t; i < c; i += 1024) { sv[i] = g_cand_val[i]; si[i] = g_cand_idx[i]; }
    for (int i = t; i < 4096; i += 1024) sh[i] = 0;
    __syncthreads();
    for (int i = t; i < c; i += 1024) {
        int q = qval(sv[i]);
        if ((q >> 12) == bstar) atomicAdd(&sh[q & 4095], 1u);
    }
    __syncthreads();
    unsigned int c4[4], s = 0;
    #pragma unroll
    for (int j = 0; j < 4; j++) { c4[j] = sh[t*4+j]; s += c4[j]; }
    unsigned int run = block_excl_scan(s, wsum);
    #pragma unroll
    for (int j = 0; j < 4; j++) {
        unsigned int cc = c4[j];
        if (run < (unsigned)need && run + cc >= (unsigned)need) { s_b2 = t*4+j; s_need2 = need - (int)run; }
        run += cc;
    }
    __syncthreads();
    int b2 = s_b2, need2 = s_need2;
    for (int j = t; j < c; j += 1024) {
        float vj = sv[j];
        int qj = qval(vj);
        if ((qj >> 12) != bstar || (qj & 4095) != b2) continue;
        int ij = si[j], cnt = 0;
        for (int i = 0; i < c; i++) {
            float v = sv[i];
            int qi = qval(v);
            if ((qi >> 12) != bstar || (qi & 4095) != b2) continue;
            cnt += (v < vj) || (v == vj && si[i] < ij);
        }
        if (cnt == need2 - 1) { g_tval = vj; g_tidx = ij; }
    }
}

__global__ void biasmask_kernel(const float* __restrict__ b, const float* __restrict__ mb) {
    __shared__ float svv[DIM];
    int t = threadIdx.x, j = blockIdx.x*256 + t;
    for (int i = t; i < DIM; i += 256) svv[i] = mb[i];
    __syncthreads();
    float vj = svv[j];
    int cnt = 0;
    for (int i = 0; i < DIM; i++) { float v = svv[i]; cnt += (v < vj) || (v == vj && i < j); }
    g_bm[j] = (cnt < KB_TOT) ? 0.0f : b[j];
}

// mask + single-limb fp16 convert of W (row stride 4096)
__global__ void maskconv_kernel(const float4* __restrict__ W4, const float4* __restrict__ M4) {
    float tv = g_tval; int ti = g_tidx;
    int stride = gridDim.x * blockDim.x;
    unsigned short* Wo = (unsigned short*)g_Wm;
    for (int i = blockIdx.x*blockDim.x + threadIdx.x; i < NUMEL/4; i += stride) {
        float4 w = W4[i]; float4 m = M4[i];
        float wv[4] = {w.x, w.y, w.z, w.w};
        float mv[4] = {m.x, m.y, m.z, m.w};
        int e0 = i*4;
        unsigned short hh[4];
        #pragma unroll
        for (int j = 0; j < 4; j++) {
            bool z = (mv[j] < tv) || (mv[j] == tv && (e0+j) <= ti);
            hh[j] = __half_as_ushort(__float2half(z ? 0.0f : wv[j]));
        }
        *(ushort4*)(Wo + (size_t)(e0>>12)*4096 + (e0 & 4095)) = make_ushort4(hh[0],hh[1],hh[2],hh[3]);
    }
}

__global__ void split_x_kernel(const float4* __restrict__ x4) {
    int stride = gridDim.x * blockDim.x;
    unsigned short* Ao = (unsigned short*)g_A0;
    for (int i = blockIdx.x*blockDim.x + threadIdx.x; i < NUMEL/4; i += stride) {
        float4 v = x4[i];
        float vv[4] = {v.x, v.y, v.z, v.w};
        unsigned short hh[4], ll[4];
        #pragma unroll
        for (int j = 0; j < 4; j++) split_fp16(vv[j], hh[j], ll[j]);
        int e0 = i*4;
        size_t base = (size_t)(e0>>12)*8192 + (e0 & 4095);
        *(ushort4*)(Ao + base)        = make_ushort4(hh[0],hh[1],hh[2],hh[3]);
        *(ushort4*)(Ao + base + 4096) = make_ushort4(ll[0],ll[1],ll[2],ll[3]);
    }
}

// ---------------- GEMM: mma.sync fp16, 256x128 tile, K=64/stage, ext-K 8192 ----------------
#define LDSM4(r, a) asm volatile("ldmatrix.sync.aligned.m8n8.x4.shared.b16 {%0,%1,%2,%3}, [%4];" \
    : "=r"((r)[0]),"=r"((r)[1]),"=r"((r)[2]),"=r"((r)[3]) : "r"(a))
#define MMA16816(acc, a, b0, b1) asm volatile( \
    "mma.sync.aligned.m16n8k16.row.col.f32.f16.f16.f32 {%0,%1,%2,%3},{%4,%5,%6,%7},{%8,%9},{%0,%1,%2,%3};" \
    : "+f"((acc)[0]),"+f"((acc)[1]),"+f"((acc)[2]),"+f"((acc)[3]) \
    : "r"((a)[0]),"r"((a)[1]),"r"((a)[2]),"r"((a)[3]),"r"(b0),"r"(b1))

template <bool FINAL>
__global__ void __launch_bounds__(512, 1) gemm_fb(
    const __half* __restrict__ A,
    unsigned short* __restrict__ outb, float* __restrict__ outf)
{
    extern __shared__ char smem[];
    uint32_t sb = smem_u32(smem);
    float* sbias = (float*)smem;
    int tid = threadIdx.x, wid = tid >> 5, lane = tid & 31;
    int mw = wid >> 2, nw = wid & 3;
    int tn = blockIdx.x, tm = blockIdx.y;
    if (tid < FN) sbias[tid] = g_bm[tn*FN + tid];

    const char* Ab = (const char*)A;
    const char* Wb = (const char*)g_Wm;

    float acc[4][4][4];
    #pragma unroll
    for (int i = 0; i < 4; i++)
        #pragma unroll
        for (int j = 0; j < 4; j++)
            #pragma unroll
            for (int k = 0; k < 4; k++) acc[i][j][k] = 0.f;

    // seg0: (Ah,Bh)  seg1: (Al,Bh).  A row stride 8192 fp16, W row stride 4096 fp16.
    #define FLOAD(s) do { \
        int seg_ = (s) >> 6, kk_ = ((s) & 63) << 6; \
        int aoff_ = (seg_ ? 4096 : 0) + kk_; \
        uint32_t stg_ = sb + 1024 + ((s) & 3) * FS_SZ; \
        for (int u = tid; u < 3072; u += 512) { \
            if (u < 2048) { int r_ = u >> 3, c_ = u & 7; \
                cp16(stg_ + SOFF(r_, c_), Ab + (((size_t)(tm*FM + r_))*8192 + aoff_ + c_*8)*2); \
            } else { int v_ = u - 2048, r_ = v_ >> 3, c_ = v_ & 7; \
                cp16(stg_ + FA_SZ + SOFF(r_, c_), Wb + (((size_t)(tn*FN + r_))*4096 + kk_ + c_*8)*2); } \
        } \
        CP_COMMIT(); \
    } while (0)

    FLOAD(0); FLOAD(1); FLOAD(2);

    int rA = mw*64 + (lane & 15);
    int rB = nw*32 + (lane & 15);
    int chh = lane >> 4;

    for (int s = 0; s < NSTAGE_F; s++) {
        if (s < NSTAGE_F-2)       { CP_WAIT(2); }
        else if (s == NSTAGE_F-2) { CP_WAIT(1); }
        else                      { CP_WAIT(0); }
        __syncthreads();
        if (s + 3 < NSTAGE_F) FLOAD(s + 3);
        uint32_t astg = sb + 1024 + (s & 3) * FS_SZ;
        uint32_t bstg = astg + FA_SZ;
        #pragma unroll
        for (int ks = 0; ks < 4; ks++) {
            int ch = ks*2 + chh;
            uint32_t a[4][4], b[2][4];
            #pragma unroll
            for (int mt = 0; mt < 4; mt++) LDSM4(a[mt], astg + SOFF(rA + mt*16, ch));
            #pragma unroll
            for (int nt = 0; nt < 2; nt++) LDSM4(b[nt], bstg + SOFF(rB + nt*16, ch));
            #pragma unroll
            for (int mt = 0; mt < 4; mt++)
                #pragma unroll
                for (int nt = 0; nt < 2; nt++)
                    #pragma unroll
                    for (int h = 0; h < 2; h++)
                        MMA16816(acc[mt][nt*2+h], a[mt], b[nt][h], b[nt][h+2]);
        }
    }

    int mwb = tm*FM + mw*64;
    #pragma unroll
    for (int mt = 0; mt < 4; mt++)
        #pragma unroll
        for (int nt = 0; nt < 2; nt++)
            #pragma unroll
            for (int h = 0; h < 2; h++) {
                float* c = acc[mt][nt*2+h];
                int m0 = mwb + mt*16 + (lane >> 2);
                int nl = nw*32 + nt*16 + h*8 + (lane & 3)*2;
                int ng = tn*FN + nl;
                float b0 = sbias[nl], b1 = sbias[nl+1];
                #pragma unroll
                for (int rr = 0; rr < 2; rr++) {
                    int m = m0 + rr*8;
                    float v0 = c[rr*2+0] + b0, v1 = c[rr*2+1] + b1;
                    if (!FINAL) {
                        unsigned short h0, l0, h1, l1;
                        split_fp16(fmaxf(v0, 0.f), h0, l0);
                        split_fp16(fmaxf(v1, 0.f), h1, l1);
                        size_t base = (size_t)m*8192 + ng;
                        *(unsigned int*)(outb + base)        = (unsigned int)h0 | ((unsigned int)h1 << 16);
                        *(unsigned int*)(outb + base + 4096) = (unsigned int)l0 | ((unsigned int)l1 << 16);
                    } else {
                        *(float2*)(outf + (size_t)m*4096 + ng) = make_float2(v0, v1);
                    }
                }
            }
}

// ---------------- launch (serial, R6 structure) ----------------
extern "C" void kernel_launch(void* const* d_in, const int* in_sizes, int n_in,
                              void* d_out, int out_size) {
    (void)in_sizes; (void)n_in; (void)out_size;
    cudaFuncSetAttribute(select_kernel, cudaFuncAttributeMaxDynamicSharedMemorySize, SEL_SMEM);
    cudaFuncSetAttribute(gemm_fb<false>, cudaFuncAttributeMaxDynamicSharedMemorySize, FB_SMEM);
    cudaFuncSetAttribute(gemm_fb<true>,  cudaFuncAttributeMaxDynamicSharedMemorySize, FB_SMEM);

    void *pA0, *pA1;
    cudaGetSymbolAddress(&pA0, g_A0);
    cudaGetSymbolAddress(&pA1, g_A1);
    __half* bufs[2] = {(__half*)pA0, (__half*)pA1};

    split_x_kernel<<<1024, 256>>>((const float4*)d_in[0]);

    for (int l = 0; l < 4; l++) {
        const float* W  = (const float*)d_in[1 + l*4 + 0];
        const float* b  = (const float*)d_in[1 + l*4 + 1];
        const float* M  = (const float*)d_in[1 + l*4 + 2];
        const float* mb = (const float*)d_in[1 + l*4 + 3];

        clear_kernel<<<1, 1024>>>();
        hist_kernel<<<1024, 256>>>((const float4*)M);
        scan_kernel<<<1, 1024>>>();
        gather_kernel<<<1024, 256>>>((const float4*)M);
        select_kernel<<<1, 1024, SEL_SMEM>>>();
        biasmask_kernel<<<16, 256>>>(b, mb);
        maskconv_kernel<<<1024, 256>>>((const float4*)W, (const float4*)M);

        dim3 gf(DIM/FN, DIM/FM);   // 32 x 16 = 512 CTAs
        const __half* Ain = bufs[l & 1];
        if (l == 3)
            gemm_fb<true><<<gf, 512, FB_SMEM>>>(Ain, nullptr, (float*)d_out);
        else
            gemm_fb<false><<<gf, 512, FB_SMEM>>>(Ain, (unsigned short*)bufs[(l+1) & 1], nullptr);
    }
}

// round 15
// speedup vs baseline: 3.1224x; 2.5551x over previous
#include <cuda_runtime.h>
#include <cuda_fp16.h>
#include <cstdint>

#define DIM      4096
#define NUMEL    (DIM*DIM)
#define KTOT     8388608u
#define KB_TOT   2048
#define NBINS    8192
#define CAP      16384
#define SEL_SMEM  (CAP*8 + 4096*4)

// GEMM: 256x128 tile, 512 threads (16 warps 4x4), K=64/stage, 4 bufs, 64 stages (K=4096)
#define FM       256
#define FN       128
#define NSTAGE_F 64
#define FA_SZ    (FM*128)
#define FB_SZ    (FN*128)
#define FS_SZ    (FA_SZ+FB_SZ)     // 49152
#define FB_SMEM  (1024 + 4*FS_SZ)  // 197632

#define SOFF(r,c) ((uint32_t)((r)*128 + (((c) ^ ((r)&7))*16)))

__device__ __half g_A0[(size_t)DIM*4096];   // activations, single fp16 limb
__device__ __half g_A1[(size_t)DIM*4096];
__device__ __half g_Wm[(size_t)DIM*4096];   // masked weights, single fp16 limb
__device__ unsigned int g_hist[NBINS];
__device__ int   g_binstar, g_cbefore, g_cand_cnt, g_spec_ok;
__device__ float g_cand_val[CAP];
__device__ int   g_cand_idx[CAP];
__device__ float g_tval;
__device__ int   g_tidx;
__device__ float g_bm[DIM];

__device__ __forceinline__ uint32_t smem_u32(const void* p) {
    uint32_t a;
    asm("{ .reg .u64 t; cvta.to.shared.u64 t, %1; cvt.u32.u64 %0, t; }" : "=r"(a) : "l"(p));
    return a;
}
__device__ __forceinline__ void cp16(uint32_t dst, const void* src) {
    asm volatile("cp.async.cg.shared.global [%0], [%1], 16;" :: "r"(dst), "l"(src));
}
#define CP_COMMIT() asm volatile("cp.async.commit_group;" ::: "memory")
#define CP_WAIT(n)  asm volatile("cp.async.wait_group %0;" :: "n"(n) : "memory")

__device__ __forceinline__ int qval(float v) {
    int q = (int)(v * 33554432.0f);
    return q < 0 ? 0 : (q > 33554431 ? 33554431 : q);
}
__device__ __forceinline__ unsigned int block_excl_scan(unsigned int val, unsigned int* wsum) {
    int lane = threadIdx.x & 31, warp = threadIdx.x >> 5;
    unsigned int v = val;
    #pragma unroll
    for (int o = 1; o < 32; o <<= 1) {
        unsigned int n = __shfl_up_sync(0xFFFFFFFFu, v, o);
        if (lane >= o) v += n;
    }
    if (lane == 31) wsum[warp] = v;
    __syncthreads();
    if (warp == 0) {
        unsigned int w = wsum[lane];
        #pragma unroll
        for (int o = 1; o < 32; o <<= 1) {
            unsigned int n = __shfl_up_sync(0xFFFFFFFFu, w, o);
            if (lane >= o) w += n;
        }
        wsum[lane] = w;
    }
    __syncthreads();
    return (warp ? wsum[warp-1] : 0u) + v - val;
}

// ---------------- masking pipeline ----------------
__global__ void clear_kernel() {
    for (int i = threadIdx.x; i < NBINS; i += 1024) g_hist[i] = 0;
    if (threadIdx.x == 0) g_cand_cnt = 0;
}

// histogram + speculative candidate gather for bins 4095..4097 (threshold ~ median)
__global__ void hist_kernel(const float4* __restrict__ M4) {
    __shared__ unsigned int h[NBINS];
    for (int i = threadIdx.x; i < NBINS; i += 256) h[i] = 0;
    __syncthreads();
    int stride = gridDim.x * blockDim.x;
    for (int i = blockIdx.x*blockDim.x + threadIdx.x; i < NUMEL/4; i += stride) {
        float4 v = M4[i];
        float vv[4] = {v.x, v.y, v.z, v.w};
        #pragma unroll
        for (int j = 0; j < 4; j++) {
            int q = qval(vv[j]), bb = q >> 12;
            atomicAdd(&h[bb], 1u);
            if (bb >= 4095 && bb <= 4097) {
                int p = atomicAdd(&g_cand_cnt, 1);
                if (p < CAP) { g_cand_val[p] = vv[j]; g_cand_idx[p] = i*4+j; }
            }
        }
    }
    __syncthreads();
    for (int i = threadIdx.x; i < NBINS; i += 256)
        if (h[i]) atomicAdd(&g_hist[i], h[i]);
}

__global__ void scan_kernel() {
    __shared__ unsigned int wsum[32];
    int t = threadIdx.x;
    unsigned int c8[8], s = 0;
    #pragma unroll
    for (int j = 0; j < 8; j++) { c8[j] = g_hist[t*8+j]; s += c8[j]; }
    unsigned int run = block_excl_scan(s, wsum);
    #pragma unroll
    for (int j = 0; j < 8; j++) {
        unsigned int c = c8[j];
        if (run < KTOT && run + c >= KTOT) {
            int bs = t*8+j;
            g_binstar = bs; g_cbefore = (int)run;
            int ok = (bs >= 4095 && bs <= 4097 && g_cand_cnt <= CAP) ? 1 : 0;
            g_spec_ok = ok;
            if (!ok) g_cand_cnt = 0;   // speculation missed: regather exactly
        }
        run += c;
    }
}

__global__ void gather_kernel(const float4* __restrict__ M4) {
    if (g_spec_ok) return;
    int bstar = g_binstar;
    int stride = gridDim.x * blockDim.x;
    for (int i = blockIdx.x*blockDim.x + threadIdx.x; i < NUMEL/4; i += stride) {
        float4 v = M4[i];
        float vv[4] = {v.x, v.y, v.z, v.w};
        #pragma unroll
        for (int j = 0; j < 4; j++)
            if ((qval(vv[j])>>12) == bstar) {
                int p = atomicAdd(&g_cand_cnt, 1);
                if (p < CAP) { g_cand_val[p] = vv[j]; g_cand_idx[p] = i*4+j; }
            }
    }
}

// exact stable-rank selection inside boundary bin (filters non-binstar candidates)
__global__ void select_kernel() {
    extern __shared__ char sm[];
    float* sv = (float*)sm;
    int* si = (int*)(sm + CAP*4);
    unsigned int* sh = (unsigned int*)(sm + CAP*8);
    __shared__ unsigned int wsum[32];
    __shared__ int s_b2, s_need2;
    int t = threadIdx.x;
    int c = g_cand_cnt; if (c > CAP) c = CAP;
    int need = (int)KTOT - g_cbefore;
    int bstar = g_binstar;
    for (int i = t; i < c; i += 1024) { sv[i] = g_cand_val[i]; si[i] = g_cand_idx[i]; }
    for (int i = t; i < 4096; i += 1024) sh[i] = 0;
    __syncthreads();
    for (int i = t; i < c; i += 1024) {
        int q = qval(sv[i]);
        if ((q >> 12) == bstar) atomicAdd(&sh[q & 4095], 1u);
    }
    __syncthreads();
    unsigned int c4[4], s = 0;
    #pragma unroll
    for (int j = 0; j < 4; j++) { c4[j] = sh[t*4+j]; s += c4[j]; }
    unsigned int run = block_excl_scan(s, wsum);
    #pragma unroll
    for (int j = 0; j < 4; j++) {
        unsigned int cc = c4[j];
        if (run < (unsigned)need && run + cc >= (unsigned)need) { s_b2 = t*4+j; s_need2 = need - (int)run; }
        run += cc;
    }
    __syncthreads();
    int b2 = s_b2, need2 = s_need2;
    for (int j = t; j < c; j += 1024) {
        float vj = sv[j];
        int qj = qval(vj);
        if ((qj >> 12) != bstar || (qj & 4095) != b2) continue;
        int ij = si[j], cnt = 0;
        for (int i = 0; i < c; i++) {
            float v = sv[i];
            int qi = qval(v);
            if ((qi >> 12) != bstar || (qi & 4095) != b2) continue;
            cnt += (v < vj) || (v == vj && si[i] < ij);
        }
        if (cnt == need2 - 1) { g_tval = vj; g_tidx = ij; }
    }
}

__global__ void biasmask_kernel(const float* __restrict__ b, const float* __restrict__ mb) {
    __shared__ float svv[DIM];
    int t = threadIdx.x, j = blockIdx.x*256 + t;
    for (int i = t; i < DIM; i += 256) svv[i] = mb[i];
    __syncthreads();
    float vj = svv[j];
    int cnt = 0;
    for (int i = 0; i < DIM; i++) { float v = svv[i]; cnt += (v < vj) || (v == vj && i < j); }
    g_bm[j] = (cnt < KB_TOT) ? 0.0f : b[j];
}

// mask + fp16 convert of W (row stride 4096)
__global__ void maskconv_kernel(const float4* __restrict__ W4, const float4* __restrict__ M4) {
    float tv = g_tval; int ti = g_tidx;
    int stride = gridDim.x * blockDim.x;
    unsigned short* Wo = (unsigned short*)g_Wm;
    for (int i = blockIdx.x*blockDim.x + threadIdx.x; i < NUMEL/4; i += stride) {
        float4 w = W4[i]; float4 m = M4[i];
        float wv[4] = {w.x, w.y, w.z, w.w};
        float mv[4] = {m.x, m.y, m.z, m.w};
        int e0 = i*4;
        unsigned short hh[4];
        #pragma unroll
        for (int j = 0; j < 4; j++) {
            bool z = (mv[j] < tv) || (mv[j] == tv && (e0+j) <= ti);
            hh[j] = __half_as_ushort(__float2half(z ? 0.0f : wv[j]));
        }
        *(ushort4*)(Wo + (size_t)(e0>>12)*4096 + (e0 & 4095)) = make_ushort4(hh[0],hh[1],hh[2],hh[3]);
    }
}

__global__ void split_x_kernel(const float4* __restrict__ x4) {
    int stride = gridDim.x * blockDim.x;
    unsigned short* Ao = (unsigned short*)g_A0;
    for (int i = blockIdx.x*blockDim.x + threadIdx.x; i < NUMEL/4; i += stride) {
        float4 v = x4[i];
        unsigned short hh[4];
        hh[0] = __half_as_ushort(__float2half(v.x));
        hh[1] = __half_as_ushort(__float2half(v.y));
        hh[2] = __half_as_ushort(__float2half(v.z));
        hh[3] = __half_as_ushort(__float2half(v.w));
        int e0 = i*4;
        *(ushort4*)(Ao + (size_t)(e0>>12)*4096 + (e0 & 4095)) = make_ushort4(hh[0],hh[1],hh[2],hh[3]);
    }
}

// ---------------- GEMM: mma.sync fp16, 256x128 tile, K=64/stage, K=4096 ----------------
#define LDSM4(r, a) asm volatile("ldmatrix.sync.aligned.m8n8.x4.shared.b16 {%0,%1,%2,%3}, [%4];" \
    : "=r"((r)[0]),"=r"((r)[1]),"=r"((r)[2]),"=r"((r)[3]) : "r"(a))
#define MMA16816(acc, a, b0, b1) asm volatile( \
    "mma.sync.aligned.m16n8k16.row.col.f32.f16.f16.f32 {%0,%1,%2,%3},{%4,%5,%6,%7},{%8,%9},{%0,%1,%2,%3};" \
    : "+f"((acc)[0]),"+f"((acc)[1]),"+f"((acc)[2]),"+f"((acc)[3]) \
    : "r"((a)[0]),"r"((a)[1]),"r"((a)[2]),"r"((a)[3]),"r"(b0),"r"(b1))

template <bool FINAL>
__global__ void __launch_bounds__(512, 1) gemm_fb(
    const __half* __restrict__ A,
    unsigned short* __restrict__ outb, float* __restrict__ outf)
{
    extern __shared__ char smem[];
    uint32_t sb = smem_u32(smem);
    float* sbias = (float*)smem;
    int tid = threadIdx.x, wid = tid >> 5, lane = tid & 31;
    int mw = wid >> 2, nw = wid & 3;
    int tn = blockIdx.x, tm = blockIdx.y;
    if (tid < FN) sbias[tid] = g_bm[tn*FN + tid];

    const char* Ab = (const char*)A;
    const char* Wb = (const char*)g_Wm;

    float acc[4][4][4];
    #pragma unroll
    for (int i = 0; i < 4; i++)
        #pragma unroll
        for (int j = 0; j < 4; j++)
            #pragma unroll
            for (int k = 0; k < 4; k++) acc[i][j][k] = 0.f;

    // A row stride 4096 fp16, W row stride 4096 fp16.
    #define FLOAD(s) do { \
        int kk_ = (s) << 6; \
        uint32_t stg_ = sb + 1024 + ((s) & 3) * FS_SZ; \
        for (int u = tid; u < 3072; u += 512) { \
            if (u < 2048) { int r_ = u >> 3, c_ = u & 7; \
                cp16(stg_ + SOFF(r_, c_), Ab + (((size_t)(tm*FM + r_))*4096 + kk_ + c_*8)*2); \
            } else { int v_ = u - 2048, r_ = v_ >> 3, c_ = v_ & 7; \
                cp16(stg_ + FA_SZ + SOFF(r_, c_), Wb + (((size_t)(tn*FN + r_))*4096 + kk_ + c_*8)*2); } \
        } \
        CP_COMMIT(); \
    } while (0)

    FLOAD(0); FLOAD(1); FLOAD(2);

    int rA = mw*64 + (lane & 15);
    int rB = nw*32 + (lane & 15);
    int chh = lane >> 4;

    for (int s = 0; s < NSTAGE_F; s++) {
        if (s < NSTAGE_F-2)       { CP_WAIT(2); }
        else if (s == NSTAGE_F-2) { CP_WAIT(1); }
        else                      { CP_WAIT(0); }
        __syncthreads();
        if (s + 3 < NSTAGE_F) FLOAD(s + 3);
        uint32_t astg = sb + 1024 + (s & 3) * FS_SZ;
        uint32_t bstg = astg + FA_SZ;
        #pragma unroll
        for (int ks = 0; ks < 4; ks++) {
            int ch = ks*2 + chh;
            uint32_t a[4][4], b[2][4];
            #pragma unroll
            for (int mt = 0; mt < 4; mt++) LDSM4(a[mt], astg + SOFF(rA + mt*16, ch));
            #pragma unroll
            for (int nt = 0; nt < 2; nt++) LDSM4(b[nt], bstg + SOFF(rB + nt*16, ch));
            #pragma unroll
            for (int mt = 0; mt < 4; mt++)
                #pragma unroll
                for (int nt = 0; nt < 2; nt++)
                    #pragma unroll
                    for (int h = 0; h < 2; h++)
                        MMA16816(acc[mt][nt*2+h], a[mt], b[nt][h], b[nt][h+2]);
        }
    }

    int mwb = tm*FM + mw*64;
    #pragma unroll
    for (int mt = 0; mt < 4; mt++)
        #pragma unroll
        for (int nt = 0; nt < 2; nt++)
            #pragma unroll
            for (int h = 0; h < 2; h++) {
                float* c = acc[mt][nt*2+h];
                int m0 = mwb + mt*16 + (lane >> 2);
                int nl = nw*32 + nt*16 + h*8 + (lane & 3)*2;
                int ng = tn*FN + nl;
                float b0 = sbias[nl], b1 = sbias[nl+1];
                #pragma unroll
                for (int rr = 0; rr < 2; rr++) {
                    int m = m0 + rr*8;
                    float v0 = c[rr*2+0] + b0, v1 = c[rr*2+1] + b1;
                    if (!FINAL) {
                        unsigned short h0 = __half_as_ushort(__float2half(fmaxf(v0, 0.f)));
                        unsigned short h1 = __half_as_ushort(__float2half(fmaxf(v1, 0.f)));
                        *(unsigned int*)(outb + (size_t)m*4096 + ng) =
                            (unsigned int)h0 | ((unsigned int)h1 << 16);
                    } else {
                        *(float2*)(outf + (size_t)m*4096 + ng) = make_float2(v0, v1);
                    }
                }
            }
}

// ---------------- launch (serial, R6 structure) ----------------
extern "C" void kernel_launch(void* const* d_in, const int* in_sizes, int n_in,
                              void* d_out, int out_size) {
    (void)in_sizes; (void)n_in; (void)out_size;
    cudaFuncSetAttribute(select_kernel, cudaFuncAttributeMaxDynamicSharedMemorySize, SEL_SMEM);
    cudaFuncSetAttribute(gemm_fb<false>, cudaFuncAttributeMaxDynamicSharedMemorySize, FB_SMEM);
    cudaFuncSetAttribute(gemm_fb<true>,  cudaFuncAttributeMaxDynamicSharedMemorySize, FB_SMEM);

    void *pA0, *pA1;
    cudaGetSymbolAddress(&pA0, g_A0);
    cudaGetSymbolAddress(&pA1, g_A1);
    __half* bufs[2] = {(__half*)pA0, (__half*)pA1};

    split_x_kernel<<<1024, 256>>>((const float4*)d_in[0]);

    for (int l = 0; l < 4; l++) {
        const float* W  = (const float*)d_in[1 + l*4 + 0];
        const float* b  = (const float*)d_in[1 + l*4 + 1];
        const float* M  = (const float*)d_in[1 + l*4 + 2];
        const float* mb = (const float*)d_in[1 + l*4 + 3];

        clear_kernel<<<1, 1024>>>();
        hist_kernel<<<1024, 256>>>((const float4*)M);
        scan_kernel<<<1, 1024>>>();
        gather_kernel<<<1024, 256>>>((const float4*)M);
        select_kernel<<<1, 1024, SEL_SMEM>>>();
        biasmask_kernel<<<16, 256>>>(b, mb);
        maskconv_kernel<<<1024, 256>>>((const float4*)W, (const float4*)M);

        dim3 gf(DIM/FN, DIM/FM);   // 32 x 16 = 512 CTAs
        const __half* Ain = bufs[l & 1];
        if (l == 3)
            gemm_fb<true><<<gf, 512, FB_SMEM>>>(Ain, nullptr, (float*)d_out);
        else
            gemm_fb<false><<<gf, 512, FB_SMEM>>>(Ain, (unsigned short*)bufs[(l+1) & 1], nullptr);
    }
}

// round 16
// speedup vs baseline: 3.1306x; 1.0026x over previous
#include <cuda_runtime.h>
#include <cuda_fp16.h>
#include <cstdint>

#define DIM      4096
#define NUMEL    (DIM*DIM)
#define KTOT     8388608u
#define KB_TOT   2048
#define NBINS    8192
#define CAP      16384
#define SEL_SMEM  (CAP*8 + 4096*4)

// GEMM: 256x128 tile, 512 threads (16 warps 4x4), K=64/stage, 4 bufs, 64 stages (K=4096)
#define FM       256
#define FN       128
#define NSTAGE_F 64
#define FA_SZ    (FM*128)
#define FB_SZ    (FN*128)
#define FS_SZ    (FA_SZ+FB_SZ)     // 49152
#define FB_SMEM  (1024 + 4*FS_SZ)  // 197632

#define SOFF(r,c) ((uint32_t)((r)*128 + (((c) ^ ((r)&7))*16)))

__device__ __half g_A0[(size_t)DIM*4096];
__device__ __half g_A1[(size_t)DIM*4096];
__device__ __half g_Wm[(size_t)DIM*4096];
__device__ unsigned int g_hist[NBINS];
__device__ unsigned int g_cbelow;       // count of bins < 4095
__device__ unsigned int g_c3[3];        // counts of bins 4095,4096,4097
__device__ int   g_binstar, g_cbefore, g_cand_cnt, g_spec_ok;
__device__ float g_cand_val[CAP];
__device__ int   g_cand_idx[CAP];
__device__ float g_tval;
__device__ int   g_tidx;
__device__ float g_bm[DIM];

__device__ __forceinline__ uint32_t smem_u32(const void* p) {
    uint32_t a;
    asm("{ .reg .u64 t; cvta.to.shared.u64 t, %1; cvt.u32.u64 %0, t; }" : "=r"(a) : "l"(p));
    return a;
}
__device__ __forceinline__ void cp16(uint32_t dst, const void* src) {
    asm volatile("cp.async.cg.shared.global [%0], [%1], 16;" :: "r"(dst), "l"(src));
}
#define CP_COMMIT() asm volatile("cp.async.commit_group;" ::: "memory")
#define CP_WAIT(n)  asm volatile("cp.async.wait_group %0;" :: "n"(n) : "memory")

__device__ __forceinline__ int qval(float v) {
    int q = (int)(v * 33554432.0f);
    return q < 0 ? 0 : (q > 33554431 ? 33554431 : q);
}
__device__ __forceinline__ unsigned int block_excl_scan(unsigned int val, unsigned int* wsum) {
    int lane = threadIdx.x & 31, warp = threadIdx.x >> 5;
    unsigned int v = val;
    #pragma unroll
    for (int o = 1; o < 32; o <<= 1) {
        unsigned int n = __shfl_up_sync(0xFFFFFFFFu, v, o);
        if (lane >= o) v += n;
    }
    if (lane == 31) wsum[warp] = v;
    __syncthreads();
    if (warp == 0) {
        unsigned int w = wsum[lane];
        #pragma unroll
        for (int o = 1; o < 32; o <<= 1) {
            unsigned int n = __shfl_up_sync(0xFFFFFFFFu, w, o);
            if (lane >= o) w += n;
        }
        wsum[lane] = w;
    }
    __syncthreads();
    return (warp ? wsum[warp-1] : 0u) + v - val;
}

// ---------------- masking pipeline ----------------
__global__ void zero_kernel() {
    if (threadIdx.x == 0) { g_cbelow = 0; g_cand_cnt = 0; }
    if (threadIdx.x < 3) g_c3[threadIdx.x] = 0;
}

// cheap speculative pass: count below-4095 + bins 4095..4097 exactly, gather their candidates
__global__ void count_kernel(const float4* __restrict__ M4) {
    unsigned int below = 0, c0 = 0, c1 = 0, c2 = 0;
    int stride = gridDim.x * blockDim.x;
    for (int i = blockIdx.x*blockDim.x + threadIdx.x; i < NUMEL/4; i += stride) {
        float4 v = M4[i];
        float vv[4] = {v.x, v.y, v.z, v.w};
        #pragma unroll
        for (int j = 0; j < 4; j++) {
            int q = qval(vv[j]), bb = q >> 12;
            below += (bb < 4095);
            if (bb >= 4095 && bb <= 4097) {
                c0 += (bb == 4095); c1 += (bb == 4096); c2 += (bb == 4097);
                int p = atomicAdd(&g_cand_cnt, 1);
                if (p < CAP) { g_cand_val[p] = vv[j]; g_cand_idx[p] = i*4+j; }
            }
        }
    }
    #pragma unroll
    for (int o = 16; o; o >>= 1) {
        below += __shfl_xor_sync(0xFFFFFFFFu, below, o);
        c0 += __shfl_xor_sync(0xFFFFFFFFu, c0, o);
        c1 += __shfl_xor_sync(0xFFFFFFFFu, c1, o);
        c2 += __shfl_xor_sync(0xFFFFFFFFu, c2, o);
    }
    if ((threadIdx.x & 31) == 0) {
        if (below) atomicAdd(&g_cbelow, below);
        if (c0) atomicAdd(&g_c3[0], c0);
        if (c1) atomicAdd(&g_c3[1], c1);
        if (c2) atomicAdd(&g_c3[2], c2);
    }
}

// validate speculation; on miss, reset for exact fallback
__global__ void check_kernel() {
    unsigned int run = g_cbelow;
    int ok = 0;
    #pragma unroll
    for (int j = 0; j < 3; j++) {
        unsigned int c = g_c3[j];
        if (!ok && run < KTOT && run + c >= KTOT) {
            g_binstar = 4095 + j; g_cbefore = (int)run; ok = 1;
        }
        run += c;
    }
    if (g_cand_cnt > CAP) ok = 0;
    g_spec_ok = ok;
    if (!ok) g_cand_cnt = 0;
}

// ---- exact fallback chain (all early-exit when speculation hit) ----
__global__ void clear_kernel() {
    if (g_spec_ok) return;
    for (int i = threadIdx.x; i < NBINS; i += 1024) g_hist[i] = 0;
}

__global__ void hist_kernel(const float4* __restrict__ M4) {
    if (g_spec_ok) return;
    __shared__ unsigned int h[NBINS];
    for (int i = threadIdx.x; i < NBINS; i += 256) h[i] = 0;
    __syncthreads();
    int stride = gridDim.x * blockDim.x;
    for (int i = blockIdx.x*blockDim.x + threadIdx.x; i < NUMEL/4; i += stride) {
        float4 v = M4[i];
        atomicAdd(&h[qval(v.x)>>12], 1u); atomicAdd(&h[qval(v.y)>>12], 1u);
        atomicAdd(&h[qval(v.z)>>12], 1u); atomicAdd(&h[qval(v.w)>>12], 1u);
    }
    __syncthreads();
    for (int i = threadIdx.x; i < NBINS; i += 256)
        if (h[i]) atomicAdd(&g_hist[i], h[i]);
}

__global__ void scan_kernel() {
    if (g_spec_ok) return;
    __shared__ unsigned int wsum[32];
    int t = threadIdx.x;
    unsigned int c8[8], s = 0;
    #pragma unroll
    for (int j = 0; j < 8; j++) { c8[j] = g_hist[t*8+j]; s += c8[j]; }
    unsigned int run = block_excl_scan(s, wsum);
    #pragma unroll
    for (int j = 0; j < 8; j++) {
        unsigned int c = c8[j];
        if (run < KTOT && run + c >= KTOT) { g_binstar = t*8+j; g_cbefore = (int)run; }
        run += c;
    }
}

__global__ void gather_kernel(const float4* __restrict__ M4) {
    if (g_spec_ok) return;
    int bstar = g_binstar;
    int stride = gridDim.x * blockDim.x;
    for (int i = blockIdx.x*blockDim.x + threadIdx.x; i < NUMEL/4; i += stride) {
        float4 v = M4[i];
        float vv[4] = {v.x, v.y, v.z, v.w};
        #pragma unroll
        for (int j = 0; j < 4; j++)
            if ((qval(vv[j])>>12) == bstar) {
                int p = atomicAdd(&g_cand_cnt, 1);
                if (p < CAP) { g_cand_val[p] = vv[j]; g_cand_idx[p] = i*4+j; }
            }
    }
}

// exact stable-rank selection inside boundary bin (filters non-binstar candidates)
__global__ void select_kernel() {
    extern __shared__ char sm[];
    float* sv = (float*)sm;
    int* si = (int*)(sm + CAP*4);
    unsigned int* sh = (unsigned int*)(sm + CAP*8);
    __shared__ unsigned int wsum[32];
    __shared__ int s_b2, s_need2;
    int t = threadIdx.x;
    int c = g_cand_cnt; if (c > CAP) c = CAP;
    int need = (int)KTOT - g_cbefore;
    int bstar = g_binstar;
    for (int i = t; i < c; i += 1024) { sv[i] = g_cand_val[i]; si[i] = g_cand_idx[i]; }
    for (int i = t; i < 4096; i += 1024) sh[i] = 0;
    __syncthreads();
    for (int i = t; i < c; i += 1024) {
        int q = qval(sv[i]);
        if ((q >> 12) == bstar) atomicAdd(&sh[q & 4095], 1u);
    }
    __syncthreads();
    unsigned int c4[4], s = 0;
    #pragma unroll
    for (int j = 0; j < 4; j++) { c4[j] = sh[t*4+j]; s += c4[j]; }
    unsigned int run = block_excl_scan(s, wsum);
    #pragma unroll
    for (int j = 0; j < 4; j++) {
        unsigned int cc = c4[j];
        if (run < (unsigned)need && run + cc >= (unsigned)need) { s_b2 = t*4+j; s_need2 = need - (int)run; }
        run += cc;
    }
    __syncthreads();
    int b2 = s_b2, need2 = s_need2;
    for (int j = t; j < c; j += 1024) {
        float vj = sv[j];
        int qj = qval(vj);
        if ((qj >> 12) != bstar || (qj & 4095) != b2) continue;
        int ij = si[j], cnt = 0;
        for (int i = 0; i < c; i++) {
            float v = sv[i];
            int qi = qval(v);
            if ((qi >> 12) != bstar || (qi & 4095) != b2) continue;
            cnt += (v < vj) || (v == vj && si[i] < ij);
        }
        if (cnt == need2 - 1) { g_tval = vj; g_tidx = ij; }
    }
}

__global__ void biasmask_kernel(const float* __restrict__ b, const float* __restrict__ mb) {
    __shared__ float svv[DIM];
    int t = threadIdx.x, j = blockIdx.x*256 + t;
    for (int i = t; i < DIM; i += 256) svv[i] = mb[i];
    __syncthreads();
    float vj = svv[j];
    int cnt = 0;
    for (int i = 0; i < DIM; i++) { float v = svv[i]; cnt += (v < vj) || (v == vj && i < j); }
    g_bm[j] = (cnt < KB_TOT) ? 0.0f : b[j];
}

// mask + fp16 convert of W (row stride 4096)
__global__ void maskconv_kernel(const float4* __restrict__ W4, const float4* __restrict__ M4) {
    float tv = g_tval; int ti = g_tidx;
    int stride = gridDim.x * blockDim.x;
    unsigned short* Wo = (unsigned short*)g_Wm;
    for (int i = blockIdx.x*blockDim.x + threadIdx.x; i < NUMEL/4; i += stride) {
        float4 w = W4[i]; float4 m = M4[i];
        float wv[4] = {w.x, w.y, w.z, w.w};
        float mv[4] = {m.x, m.y, m.z, m.w};
        int e0 = i*4;
        unsigned short hh[4];
        #pragma unroll
        for (int j = 0; j < 4; j++) {
            bool z = (mv[j] < tv) || (mv[j] == tv && (e0+j) <= ti);
            hh[j] = __half_as_ushort(__float2half(z ? 0.0f : wv[j]));
        }
        *(ushort4*)(Wo + (size_t)(e0>>12)*4096 + (e0 & 4095)) = make_ushort4(hh[0],hh[1],hh[2],hh[3]);
    }
}

__global__ void split_x_kernel(const float4* __restrict__ x4) {
    int stride = gridDim.x * blockDim.x;
    unsigned short* Ao = (unsigned short*)g_A0;
    for (int i = blockIdx.x*blockDim.x + threadIdx.x; i < NUMEL/4; i += stride) {
        float4 v = x4[i];
        unsigned short hh[4];
        hh[0] = __half_as_ushort(__float2half(v.x));
        hh[1] = __half_as_ushort(__float2half(v.y));
        hh[2] = __half_as_ushort(__float2half(v.z));
        hh[3] = __half_as_ushort(__float2half(v.w));
        int e0 = i*4;
        *(ushort4*)(Ao + (size_t)(e0>>12)*4096 + (e0 & 4095)) = make_ushort4(hh[0],hh[1],hh[2],hh[3]);
    }
}

// ---------------- GEMM: mma.sync fp16, 256x128 tile, K=64/stage, K=4096 ----------------
#define LDSM4(r, a) asm volatile("ldmatrix.sync.aligned.m8n8.x4.shared.b16 {%0,%1,%2,%3}, [%4];" \
    : "=r"((r)[0]),"=r"((r)[1]),"=r"((r)[2]),"=r"((r)[3]) : "r"(a))
#define MMA16816(acc, a, b0, b1) asm volatile( \
    "mma.sync.aligned.m16n8k16.row.col.f32.f16.f16.f32 {%0,%1,%2,%3},{%4,%5,%6,%7},{%8,%9},{%0,%1,%2,%3};" \
    : "+f"((acc)[0]),"+f"((acc)[1]),"+f"((acc)[2]),"+f"((acc)[3]) \
    : "r"((a)[0]),"r"((a)[1]),"r"((a)[2]),"r"((a)[3]),"r"(b0),"r"(b1))

template <bool FINAL>
__global__ void __launch_bounds__(512, 1) gemm_fb(
    const __half* __restrict__ A,
    unsigned short* __restrict__ outb, float* __restrict__ outf)
{
    extern __shared__ char smem[];
    uint32_t sb = smem_u32(smem);
    float* sbias = (float*)smem;
    int tid = threadIdx.x, wid = tid >> 5, lane = tid & 31;
    int mw = wid >> 2, nw = wid & 3;
    int tn = blockIdx.x, tm = blockIdx.y;
    if (tid < FN) sbias[tid] = g_bm[tn*FN + tid];

    const char* Ab = (const char*)A;
    const char* Wb = (const char*)g_Wm;

    float acc[4][4][4];
    #pragma unroll
    for (int i = 0; i < 4; i++)
        #pragma unroll
        for (int j = 0; j < 4; j++)
            #pragma unroll
            for (int k = 0; k < 4; k++) acc[i][j][k] = 0.f;

    #define FLOAD(s) do { \
        int kk_ = (s) << 6; \
        uint32_t stg_ = sb + 1024 + ((s) & 3) * FS_SZ; \
        for (int u = tid; u < 3072; u += 512) { \
            if (u < 2048) { int r_ = u >> 3, c_ = u & 7; \
                cp16(stg_ + SOFF(r_, c_), Ab + (((size_t)(tm*FM + r_))*4096 + kk_ + c_*8)*2); \
            } else { int v_ = u - 2048, r_ = v_ >> 3, c_ = v_ & 7; \
                cp16(stg_ + FA_SZ + SOFF(r_, c_), Wb + (((size_t)(tn*FN + r_))*4096 + kk_ + c_*8)*2); } \
        } \
        CP_COMMIT(); \
    } while (0)

    FLOAD(0); FLOAD(1); FLOAD(2);

    int rA = mw*64 + (lane & 15);
    int rB = nw*32 + (lane & 15);
    int chh = lane >> 4;

    for (int s = 0; s < NSTAGE_F; s++) {
        if (s < NSTAGE_F-2)       { CP_WAIT(2); }
        else if (s == NSTAGE_F-2) { CP_WAIT(1); }
        else                      { CP_WAIT(0); }
        __syncthreads();
        if (s + 3 < NSTAGE_F) FLOAD(s + 3);
        uint32_t astg = sb + 1024 + (s & 3) * FS_SZ;
        uint32_t bstg = astg + FA_SZ;
        #pragma unroll
        for (int ks = 0; ks < 4; ks++) {
            int ch = ks*2 + chh;
            uint32_t a[4][4], b[2][4];
            #pragma unroll
            for (int mt = 0; mt < 4; mt++) LDSM4(a[mt], astg + SOFF(rA + mt*16, ch));
            #pragma unroll
            for (int nt = 0; nt < 2; nt++) LDSM4(b[nt], bstg + SOFF(rB + nt*16, ch));
            #pragma unroll
            for (int mt = 0; mt < 4; mt++)
                #pragma unroll
                for (int nt = 0; nt < 2; nt++)
                    #pragma unroll
                    for (int h = 0; h < 2; h++)
                        MMA16816(acc[mt][nt*2+h], a[mt], b[nt][h], b[nt][h+2]);
        }
    }

    int mwb = tm*FM + mw*64;
    #pragma unroll
    for (int mt = 0; mt < 4; mt++)
        #pragma unroll
        for (int nt = 0; nt < 2; nt++)
            #pragma unroll
            for (int h = 0; h < 2; h++) {
                float* c = acc[mt][nt*2+h];
                int m0 = mwb + mt*16 + (lane >> 2);
                int nl = nw*32 + nt*16 + h*8 + (lane & 3)*2;
                int ng = tn*FN + nl;
                float b0 = sbias[nl], b1 = sbias[nl+1];
                #pragma unroll
                for (int rr = 0; rr < 2; rr++) {
                    int m = m0 + rr*8;
                    float v0 = c[rr*2+0] + b0, v1 = c[rr*2+1] + b1;
                    if (!FINAL) {
                        unsigned short h0 = __half_as_ushort(__float2half(fmaxf(v0, 0.f)));
                        unsigned short h1 = __half_as_ushort(__float2half(fmaxf(v1, 0.f)));
                        *(unsigned int*)(outb + (size_t)m*4096 + ng) =
                            (unsigned int)h0 | ((unsigned int)h1 << 16);
                    } else {
                        *(float2*)(outf + (size_t)m*4096 + ng) = make_float2(v0, v1);
                    }
                }
            }
}

// ---------------- launch (serial) ----------------
extern "C" void kernel_launch(void* const* d_in, const int* in_sizes, int n_in,
                              void* d_out, int out_size) {
    (void)in_sizes; (void)n_in; (void)out_size;
    cudaFuncSetAttribute(select_kernel, cudaFuncAttributeMaxDynamicSharedMemorySize, SEL_SMEM);
    cudaFuncSetAttribute(gemm_fb<false>, cudaFuncAttributeMaxDynamicSharedMemorySize, FB_SMEM);
    cudaFuncSetAttribute(gemm_fb<true>,  cudaFuncAttributeMaxDynamicSharedMemorySize, FB_SMEM);

    void *pA0, *pA1;
    cudaGetSymbolAddress(&pA0, g_A0);
    cudaGetSymbolAddress(&pA1, g_A1);
    __half* bufs[2] = {(__half*)pA0, (__half*)pA1};

    split_x_kernel<<<2048, 256>>>((const float4*)d_in[0]);

    for (int l = 0; l < 4; l++) {
        const float* W  = (const float*)d_in[1 + l*4 + 0];
        const float* b  = (const float*)d_in[1 + l*4 + 1];
        const float* M  = (const float*)d_in[1 + l*4 + 2];
        const float* mb = (const float*)d_in[1 + l*4 + 3];

        zero_kernel<<<1, 32>>>();
        count_kernel<<<2048, 256>>>((const float4*)M);
        check_kernel<<<1, 1>>>();
        // exact fallback (no-ops when speculation hit)
        clear_kernel<<<1, 1024>>>();
        hist_kernel<<<1024, 256>>>((const float4*)M);
        scan_kernel<<<1, 1024>>>();
        gather_kernel<<<1024, 256>>>((const float4*)M);

        select_kernel<<<1, 1024, SEL_SMEM>>>();
        biasmask_kernel<<<16, 256>>>(b, mb);
        maskconv_kernel<<<2048, 256>>>((const float4*)W, (const float4*)M);

        dim3 gf(DIM/FN, DIM/FM);   // 32 x 16 = 512 CTAs
        const __half* Ain = bufs[l & 1];
        if (l == 3)
            gemm_fb<true><<<gf, 512, FB_SMEM>>>(Ain, nullptr, (float*)d_out);
        else
            gemm_fb<false><<<gf, 512, FB_SMEM>>>(Ain, (unsigned short*)bufs[(l+1) & 1], nullptr);
    }
}

// round 17
// speedup vs baseline: 3.3009x; 1.0544x over previous
#include <cuda_runtime.h>
#include <cuda_fp16.h>
#include <cstdint>

#define DIM      4096
#define NUMEL    (DIM*DIM)
#define KTOT     8388608u
#define KB_TOT   2048
#define NBINS    8192
#define CAP      16384
#define SEL_SMEM  (CAP*8 + 4096*4)

// GEMM: 256x128 tile, 512 threads (16 warps 4x4), K=64/stage, 4 bufs, 64 stages (K=4096)
#define FM       256
#define FN       128
#define NSTAGE_F 64
#define FA_SZ    (FM*128)
#define FB_SZ    (FN*128)
#define FS_SZ    (FA_SZ+FB_SZ)     // 49152
#define FB_SMEM  (1024 + 4*FS_SZ)  // 197632

#define SOFF(r,c) ((uint32_t)((r)*128 + (((c) ^ ((r)&7))*16)))

__device__ __half g_A0[(size_t)DIM*4096];
__device__ __half g_A1[(size_t)DIM*4096];
__device__ __half g_Wm[(size_t)DIM*4096];
__device__ uint8_t g_zb[NUMEL/4];        // zero-decision bitmap: 4 elems/byte
__device__ unsigned int g_hist[NBINS];
__device__ unsigned int g_cbelow;
__device__ unsigned int g_c3[3];
__device__ unsigned int g_done;
__device__ int   g_binstar, g_cbefore, g_cand_cnt, g_spec_ok;
__device__ float g_cand_val[CAP];
__device__ int   g_cand_idx[CAP];
__device__ float g_tval;
__device__ int   g_tidx;
__device__ float g_bm[DIM];

__device__ __forceinline__ uint32_t smem_u32(const void* p) {
    uint32_t a;
    asm("{ .reg .u64 t; cvta.to.shared.u64 t, %1; cvt.u32.u64 %0, t; }" : "=r"(a) : "l"(p));
    return a;
}
__device__ __forceinline__ void cp16(uint32_t dst, const void* src) {
    asm volatile("cp.async.cg.shared.global [%0], [%1], 16;" :: "r"(dst), "l"(src));
}
#define CP_COMMIT() asm volatile("cp.async.commit_group;" ::: "memory")
#define CP_WAIT(n)  asm volatile("cp.async.wait_group %0;" :: "n"(n) : "memory")

__device__ __forceinline__ int qval(float v) {
    int q = (int)(v * 33554432.0f);
    return q < 0 ? 0 : (q > 33554431 ? 33554431 : q);
}
__device__ __forceinline__ unsigned int block_excl_scan(unsigned int val, unsigned int* wsum) {
    int lane = threadIdx.x & 31, warp = threadIdx.x >> 5;
    unsigned int v = val;
    #pragma unroll
    for (int o = 1; o < 32; o <<= 1) {
        unsigned int n = __shfl_up_sync(0xFFFFFFFFu, v, o);
        if (lane >= o) v += n;
    }
    if (lane == 31) wsum[warp] = v;
    __syncthreads();
    if (warp == 0) {
        unsigned int w = wsum[lane];
        #pragma unroll
        for (int o = 1; o < 32; o <<= 1) {
            unsigned int n = __shfl_up_sync(0xFFFFFFFFu, w, o);
            if (lane >= o) w += n;
        }
        wsum[lane] = w;
    }
    __syncthreads();
    return (warp ? wsum[warp-1] : 0u) + v - val;
}

// ---------------- masking pipeline ----------------
__global__ void zero_kernel() {
    for (int i = threadIdx.x; i < NBINS; i += 1024) g_hist[i] = 0;
    if (threadIdx.x == 0) { g_cbelow = 0; g_cand_cnt = 0; }
    if (threadIdx.x < 3) g_c3[threadIdx.x] = 0;
}

// one pass over M: counts, candidate gather, zero-decision bitmap, last-CTA check
__global__ void count_kernel(const float4* __restrict__ M4) {
    unsigned int below = 0, c0 = 0, c1 = 0, c2 = 0;
    int stride = gridDim.x * blockDim.x;
    for (int i = blockIdx.x*blockDim.x + threadIdx.x; i < NUMEL/4; i += stride) {
        float4 v = M4[i];
        float vv[4] = {v.x, v.y, v.z, v.w};
        unsigned int zbyte = 0;
        #pragma unroll
        for (int j = 0; j < 4; j++) {
            int q = qval(vv[j]), bb = q >> 12;
            if (bb < 4095) { below++; zbyte |= (1u << j); }
            else if (bb <= 4097) {
                c0 += (bb == 4095); c1 += (bb == 4096); c2 += (bb == 4097);
                int p = atomicAdd(&g_cand_cnt, 1);
                if (p < CAP) { g_cand_val[p] = vv[j]; g_cand_idx[p] = i*4+j; }
            }
        }
        g_zb[i] = (uint8_t)zbyte;
    }
    #pragma unroll
    for (int o = 16; o; o >>= 1) {
        below += __shfl_xor_sync(0xFFFFFFFFu, below, o);
        c0 += __shfl_xor_sync(0xFFFFFFFFu, c0, o);
        c1 += __shfl_xor_sync(0xFFFFFFFFu, c1, o);
        c2 += __shfl_xor_sync(0xFFFFFFFFu, c2, o);
    }
    if ((threadIdx.x & 31) == 0) {
        if (below) atomicAdd(&g_cbelow, below);
        if (c0) atomicAdd(&g_c3[0], c0);
        if (c1) atomicAdd(&g_c3[1], c1);
        if (c2) atomicAdd(&g_c3[2], c2);
    }
    // last-CTA validation (single thread)
    __threadfence();
    __syncthreads();
    if (threadIdx.x == 0) {
        unsigned int t = atomicAdd(&g_done, 1u);
        if (t == gridDim.x - 1) {
            g_done = 0;
            unsigned int run = g_cbelow;
            int ok = 0;
            #pragma unroll
            for (int j = 0; j < 3; j++) {
                unsigned int c = g_c3[j];
                if (!ok && run < KTOT && run + c >= KTOT) {
                    g_binstar = 4095 + j; g_cbefore = (int)run; ok = 1;
                }
                run += c;
            }
            if (g_cand_cnt > CAP) ok = 0;
            g_spec_ok = ok;
            if (!ok) g_cand_cnt = 0;
        }
    }
}

// ---- exact fallback chain (early-exit when speculation hit) ----
__global__ void hist_kernel(const float4* __restrict__ M4) {
    if (g_spec_ok) return;
    __shared__ unsigned int h[NBINS];
    for (int i = threadIdx.x; i < NBINS; i += 256) h[i] = 0;
    __syncthreads();
    int stride = gridDim.x * blockDim.x;
    for (int i = blockIdx.x*blockDim.x + threadIdx.x; i < NUMEL/4; i += stride) {
        float4 v = M4[i];
        atomicAdd(&h[qval(v.x)>>12], 1u); atomicAdd(&h[qval(v.y)>>12], 1u);
        atomicAdd(&h[qval(v.z)>>12], 1u); atomicAdd(&h[qval(v.w)>>12], 1u);
    }
    __syncthreads();
    for (int i = threadIdx.x; i < NBINS; i += 256)
        if (h[i]) atomicAdd(&g_hist[i], h[i]);
}

__global__ void scan_kernel() {
    if (g_spec_ok) return;
    __shared__ unsigned int wsum[32];
    int t = threadIdx.x;
    unsigned int c8[8], s = 0;
    #pragma unroll
    for (int j = 0; j < 8; j++) { c8[j] = g_hist[t*8+j]; s += c8[j]; }
    unsigned int run = block_excl_scan(s, wsum);
    #pragma unroll
    for (int j = 0; j < 8; j++) {
        unsigned int c = c8[j];
        if (run < KTOT && run + c >= KTOT) { g_binstar = t*8+j; g_cbefore = (int)run; }
        run += c;
    }
}

__global__ void gather_kernel(const float4* __restrict__ M4) {
    if (g_spec_ok) return;
    int bstar = g_binstar;
    int stride = gridDim.x * blockDim.x;
    for (int i = blockIdx.x*blockDim.x + threadIdx.x; i < NUMEL/4; i += stride) {
        float4 v = M4[i];
        float vv[4] = {v.x, v.y, v.z, v.w};
        #pragma unroll
        for (int j = 0; j < 4; j++)
            if ((qval(vv[j])>>12) == bstar) {
                int p = atomicAdd(&g_cand_cnt, 1);
                if (p < CAP) { g_cand_val[p] = vv[j]; g_cand_idx[p] = i*4+j; }
            }
    }
}

// fused: block 0 = exact stable-rank selection; blocks 1..4 = bias masking
__global__ void selbias_kernel(const float* __restrict__ b, const float* __restrict__ mb) {
    if (blockIdx.x > 0) {
        __shared__ float svv[DIM];
        int t = threadIdx.x, j = (blockIdx.x - 1)*1024 + t;
        for (int i = t; i < DIM; i += 1024) svv[i] = mb[i];
        __syncthreads();
        float vj = svv[j];
        int cnt = 0;
        for (int i = 0; i < DIM; i++) { float v = svv[i]; cnt += (v < vj) || (v == vj && i < j); }
        g_bm[j] = (cnt < KB_TOT) ? 0.0f : b[j];
        return;
    }
    extern __shared__ char sm[];
    float* sv = (float*)sm;
    int* si = (int*)(sm + CAP*4);
    unsigned int* sh = (unsigned int*)(sm + CAP*8);
    __shared__ unsigned int wsum[32];
    __shared__ int s_b2, s_need2;
    int t = threadIdx.x;
    int c = g_cand_cnt; if (c > CAP) c = CAP;
    int need = (int)KTOT - g_cbefore;
    int bstar = g_binstar;
    for (int i = t; i < c; i += 1024) { sv[i] = g_cand_val[i]; si[i] = g_cand_idx[i]; }
    for (int i = t; i < 4096; i += 1024) sh[i] = 0;
    __syncthreads();
    for (int i = t; i < c; i += 1024) {
        int q = qval(sv[i]);
        if ((q >> 12) == bstar) atomicAdd(&sh[q & 4095], 1u);
    }
    __syncthreads();
    unsigned int c4[4], s = 0;
    #pragma unroll
    for (int j = 0; j < 4; j++) { c4[j] = sh[t*4+j]; s += c4[j]; }
    unsigned int run = block_excl_scan(s, wsum);
    #pragma unroll
    for (int j = 0; j < 4; j++) {
        unsigned int cc = c4[j];
        if (run < (unsigned)need && run + cc >= (unsigned)need) { s_b2 = t*4+j; s_need2 = need - (int)run; }
        run += cc;
    }
    __syncthreads();
    int b2 = s_b2, need2 = s_need2;
    for (int j = t; j < c; j += 1024) {
        float vj = sv[j];
        int qj = qval(vj);
        if ((qj >> 12) != bstar || (qj & 4095) != b2) continue;
        int ij = si[j], cnt = 0;
        for (int i = 0; i < c; i++) {
            float v = sv[i];
            int qi = qval(v);
            if ((qi >> 12) != bstar || (qi & 4095) != b2) continue;
            cnt += (v < vj) || (v == vj && si[i] < ij);
        }
        if (cnt == need2 - 1) { g_tval = vj; g_tidx = ij; }
    }
}

// mask + fp16 convert of W. Spec path: W + bitmap; fallback path: W + M compare.
__global__ void maskconv_kernel(const float4* __restrict__ W4, const float4* __restrict__ M4) {
    int spec = g_spec_ok;
    float tv = g_tval; int ti = g_tidx;
    int stride = gridDim.x * blockDim.x;
    unsigned short* Wo = (unsigned short*)g_Wm;
    for (int i = blockIdx.x*blockDim.x + threadIdx.x; i < NUMEL/4; i += stride) {
        float4 w = W4[i];
        float wv[4] = {w.x, w.y, w.z, w.w};
        int e0 = i*4;
        unsigned short hh[4];
        if (spec) {
            unsigned int zbits = g_zb[i];
            #pragma unroll
            for (int j = 0; j < 4; j++)
                hh[j] = __half_as_ushort(__float2half(((zbits >> j) & 1u) ? 0.0f : wv[j]));
        } else {
            float4 m = M4[i];
            float mv[4] = {m.x, m.y, m.z, m.w};
            #pragma unroll
            for (int j = 0; j < 4; j++) {
                bool z = (mv[j] < tv) || (mv[j] == tv && (e0+j) <= ti);
                hh[j] = __half_as_ushort(__float2half(z ? 0.0f : wv[j]));
            }
        }
        *(ushort4*)(Wo + (size_t)e0) = make_ushort4(hh[0],hh[1],hh[2],hh[3]);
    }
}

// exact re-decision of boundary-bin elements (spec path only; runs after maskconv)
__global__ void fixup_kernel(const float* __restrict__ W) {
    if (!g_spec_ok) return;
    float tv = g_tval; int ti = g_tidx;
    int c = g_cand_cnt; if (c > CAP) c = CAP;
    unsigned short* Wo = (unsigned short*)g_Wm;
    int stride = gridDim.x * blockDim.x;
    for (int i = blockIdx.x*blockDim.x + threadIdx.x; i < c; i += stride) {
        float v = g_cand_val[i];
        int idx = g_cand_idx[i];
        bool z = (v < tv) || (v == tv && idx <= ti);
        Wo[idx] = z ? (unsigned short)0 : __half_as_ushort(__float2half(W[idx]));
    }
}

__global__ void split_x_kernel(const float4* __restrict__ x4) {
    int stride = gridDim.x * blockDim.x;
    unsigned short* Ao = (unsigned short*)g_A0;
    for (int i = blockIdx.x*blockDim.x + threadIdx.x; i < NUMEL/4; i += stride) {
        float4 v = x4[i];
        unsigned short hh[4];
        hh[0] = __half_as_ushort(__float2half(v.x));
        hh[1] = __half_as_ushort(__float2half(v.y));
        hh[2] = __half_as_ushort(__float2half(v.z));
        hh[3] = __half_as_ushort(__float2half(v.w));
        *(ushort4*)(Ao + (size_t)i*4) = make_ushort4(hh[0],hh[1],hh[2],hh[3]);
    }
}

// ---------------- GEMM: mma.sync fp16, 256x128 tile, K=64/stage, K=4096 ----------------
#define LDSM4(r, a) asm volatile("ldmatrix.sync.aligned.m8n8.x4.shared.b16 {%0,%1,%2,%3}, [%4];" \
    : "=r"((r)[0]),"=r"((r)[1]),"=r"((r)[2]),"=r"((r)[3]) : "r"(a))
#define MMA16816(acc, a, b0, b1) asm volatile( \
    "mma.sync.aligned.m16n8k16.row.col.f32.f16.f16.f32 {%0,%1,%2,%3},{%4,%5,%6,%7},{%8,%9},{%0,%1,%2,%3};" \
    : "+f"((acc)[0]),"+f"((acc)[1]),"+f"((acc)[2]),"+f"((acc)[3]) \
    : "r"((a)[0]),"r"((a)[1]),"r"((a)[2]),"r"((a)[3]),"r"(b0),"r"(b1))

template <bool FINAL>
__global__ void __launch_bounds__(512, 1) gemm_fb(
    const __half* __restrict__ A,
    unsigned short* __restrict__ outb, float* __restrict__ outf)
{
    extern __shared__ char smem[];
    uint32_t sb = smem_u32(smem);
    float* sbias = (float*)smem;
    int tid = threadIdx.x, wid = tid >> 5, lane = tid & 31;
    int mw = wid >> 2, nw = wid & 3;
    int tn = blockIdx.x, tm = blockIdx.y;
    if (tid < FN) sbias[tid] = g_bm[tn*FN + tid];

    const char* Ab = (const char*)A;
    const char* Wb = (const char*)g_Wm;

    float acc[4][4][4];
    #pragma unroll
    for (int i = 0; i < 4; i++)
        #pragma unroll
        for (int j = 0; j < 4; j++)
            #pragma unroll
            for (int k = 0; k < 4; k++) acc[i][j][k] = 0.f;

    #define FLOAD(s) do { \
        int kk_ = (s) << 6; \
        uint32_t stg_ = sb + 1024 + ((s) & 3) * FS_SZ; \
        for (int u = tid; u < 3072; u += 512) { \
            if (u < 2048) { int r_ = u >> 3, c_ = u & 7; \
                cp16(stg_ + SOFF(r_, c_), Ab + (((size_t)(tm*FM + r_))*4096 + kk_ + c_*8)*2); \
            } else { int v_ = u - 2048, r_ = v_ >> 3, c_ = v_ & 7; \
                cp16(stg_ + FA_SZ + SOFF(r_, c_), Wb + (((size_t)(tn*FN + r_))*4096 + kk_ + c_*8)*2); } \
        } \
        CP_COMMIT(); \
    } while (0)

    FLOAD(0); FLOAD(1); FLOAD(2);

    int rA = mw*64 + (lane & 15);
    int rB = nw*32 + (lane & 15);
    int chh = lane >> 4;

    for (int s = 0; s < NSTAGE_F; s++) {
        if (s < NSTAGE_F-2)       { CP_WAIT(2); }
        else if (s == NSTAGE_F-2) { CP_WAIT(1); }
        else                      { CP_WAIT(0); }
        __syncthreads();
        if (s + 3 < NSTAGE_F) FLOAD(s + 3);
        uint32_t astg = sb + 1024 + (s & 3) * FS_SZ;
        uint32_t bstg = astg + FA_SZ;
        #pragma unroll
        for (int ks = 0; ks < 4; ks++) {
            int ch = ks*2 + chh;
            uint32_t a[4][4], b[2][4];
            #pragma unroll
            for (int mt = 0; mt < 4; mt++) LDSM4(a[mt], astg + SOFF(rA + mt*16, ch));
            #pragma unroll
            for (int nt = 0; nt < 2; nt++) LDSM4(b[nt], bstg + SOFF(rB + nt*16, ch));
            #pragma unroll
            for (int mt = 0; mt < 4; mt++)
                #pragma unroll
                for (int nt = 0; nt < 2; nt++)
                    #pragma unroll
                    for (int h = 0; h < 2; h++)
                        MMA16816(acc[mt][nt*2+h], a[mt], b[nt][h], b[nt][h+2]);
        }
    }

    int mwb = tm*FM + mw*64;
    #pragma unroll
    for (int mt = 0; mt < 4; mt++)
        #pragma unroll
        for (int nt = 0; nt < 2; nt++)
            #pragma unroll
            for (int h = 0; h < 2; h++) {
                float* c = acc[mt][nt*2+h];
                int m0 = mwb + mt*16 + (lane >> 2);
                int nl = nw*32 + nt*16 + h*8 + (lane & 3)*2;
                int ng = tn*FN + nl;
                float b0 = sbias[nl], b1 = sbias[nl+1];
                #pragma unroll
                for (int rr = 0; rr < 2; rr++) {
                    int m = m0 + rr*8;
                    float v0 = c[rr*2+0] + b0, v1 = c[rr*2+1] + b1;
                    if (!FINAL) {
                        unsigned short h0 = __half_as_ushort(__float2half(fmaxf(v0, 0.f)));
                        unsigned short h1 = __half_as_ushort(__float2half(fmaxf(v1, 0.f)));
                        *(unsigned int*)(outb + (size_t)m*4096 + ng) =
                            (unsigned int)h0 | ((unsigned int)h1 << 16);
                    } else {
                        *(float2*)(outf + (size_t)m*4096 + ng) = make_float2(v0, v1);
                    }
                }
            }
}

// ---------------- launch (serial) ----------------
extern "C" void kernel_launch(void* const* d_in, const int* in_sizes, int n_in,
                              void* d_out, int out_size) {
    (void)in_sizes; (void)n_in; (void)out_size;
    cudaFuncSetAttribute(selbias_kernel, cudaFuncAttributeMaxDynamicSharedMemorySize, SEL_SMEM);
    cudaFuncSetAttribute(gemm_fb<false>, cudaFuncAttributeMaxDynamicSharedMemorySize, FB_SMEM);
    cudaFuncSetAttribute(gemm_fb<true>,  cudaFuncAttributeMaxDynamicSharedMemorySize, FB_SMEM);

    void *pA0, *pA1;
    cudaGetSymbolAddress(&pA0, g_A0);
    cudaGetSymbolAddress(&pA1, g_A1);
    __half* bufs[2] = {(__half*)pA0, (__half*)pA1};

    split_x_kernel<<<2048, 256>>>((const float4*)d_in[0]);

    for (int l = 0; l < 4; l++) {
        const float* W  = (const float*)d_in[1 + l*4 + 0];
        const float* b  = (const float*)d_in[1 + l*4 + 1];
        const float* M  = (const float*)d_in[1 + l*4 + 2];
        const float* mb = (const float*)d_in[1 + l*4 + 3];

        zero_kernel<<<1, 1024>>>();
        count_kernel<<<2048, 256>>>((const float4*)M);
        // exact fallback (no-ops when speculation hit)
        hist_kernel<<<1024, 256>>>((const float4*)M);
        scan_kernel<<<1, 1024>>>();
        gather_kernel<<<1024, 256>>>((const float4*)M);

        selbias_kernel<<<5, 1024, SEL_SMEM>>>(b, mb);
        maskconv_kernel<<<2048, 256>>>((const float4*)W, (const float4*)M);
        fixup_kernel<<<16, 256>>>(W);

        dim3 gf(DIM/FN, DIM/FM);   // 32 x 16 = 512 CTAs
        const __half* Ain = bufs[l & 1];
        if (l == 3)
            gemm_fb<true><<<gf, 512, FB_SMEM>>>(Ain, nullptr, (float*)d_out);
        else
            gemm_fb<false><<<gf, 512, FB_SMEM>>>(Ain, (unsigned short*)bufs[(l+1) & 1], nullptr);
    }
}